// round 2
// baseline (speedup 1.0000x reference)
#include <cuda_runtime.h>
#include <math.h>

#define BB 16
#define T2 2048
#define T1 512
#define FF 128
#define NBT (BB*T2)

// scratch (allocation-free rule: __device__ globals)
__device__ float g_prop[NBT];
__device__ float g_nrm[NBT];
__device__ float g_crs[NBT];
__device__ float g_imv[NBT];   // monotone (pre-mask) imv, used for search + gamma
__device__ float g_Z[NBT];     // windowed softmax partition per frame

__device__ __forceinline__ float warpsum(float v) {
#pragma unroll
    for (int o = 16; o > 0; o >>= 1) v += __shfl_down_sync(0xffffffffu, v, o);
    return v;
}

// ---------------------------------------------------------------------------
// k1: warp per (b,t) row.
//  prop[r] = sum_s alpha[r,s]*s          (64 MB read — dominant)
//  nrm[r]  = ||mels[r,:]||
//  crs[r]  = dot(mels[r,:], mels[r+1,:]) for t < T2-1
// ---------------------------------------------------------------------------
__global__ void k1(const float* __restrict__ mels, const float* __restrict__ alpha) {
    int warp = (blockIdx.x * blockDim.x + threadIdx.x) >> 5;
    int lane = threadIdx.x & 31;
    if (warp >= NBT) return;
    int t = warp % T2;

    const float4* A = reinterpret_cast<const float4*>(alpha + (size_t)warp * T1);
    float ps = 0.f;
#pragma unroll
    for (int j = 0; j < 4; j++) {
        int i4 = j * 32 + lane;
        float4 a = A[i4];
        float base = (float)(i4 * 4);
        ps += a.x * base + a.y * (base + 1.f) + a.z * (base + 2.f) + a.w * (base + 3.f);
    }

    const float4* M = reinterpret_cast<const float4*>(mels + (size_t)warp * FF);
    float4 m = M[lane];
    float ns = m.x * m.x + m.y * m.y + m.z * m.z + m.w * m.w;
    float cs = 0.f;
    bool has_next = (t < T2 - 1);
    if (has_next) {
        float4 m2 = M[32 + lane];
        cs = m.x * m2.x + m.y * m2.y + m.z * m2.z + m.w * m2.w;
    }
    ps = warpsum(ps);
    ns = warpsum(ns);
    cs = warpsum(cs);
    if (lane == 0) {
        g_prop[warp] = ps;
        g_nrm[warp]  = sqrtf(ns);
        if (has_next) g_crs[warp] = cs;
    }
}

// ---------------------------------------------------------------------------
// k2: one block per batch. activity -> eff_delta -> block scan -> rescale ->
// write imv (output + monotone scratch) and windowed partition Z[t].
// ---------------------------------------------------------------------------
__global__ void __launch_bounds__(256) k2(const int* __restrict__ mel_mask,
                                          const int* __restrict__ text_mask,
                                          float* __restrict__ imv_out) {
    const int PER = T2 / 256;  // 8
    int b = blockIdx.x;
    int tid = threadIdx.x;

    __shared__ float s_raw[T2];
    __shared__ float s_sum[256];
    __shared__ int s_amcnt, s_tmcnt;
    __shared__ float s_scale;
    if (tid == 0) { s_amcnt = 0; s_tmcnt = 0; }
    __syncthreads();

    const float* prop = g_prop + b * T2;
    const float* nrm  = g_nrm  + b * T2;
    const float* crs  = g_crs  + b * T2;
    const int* am = mel_mask  + b * T2;
    const int* tm = text_mask + b * T1;

    float v[PER];
    float local = 0.f;
    int amc = 0;
    int base = tid * PER;
#pragma unroll
    for (int i = 0; i < PER; i++) {
        int t = base + i;
        int a = am[t];
        amc += a;
        float eff = 0.f;
        if (t > 0 && a) {
            float cosv = crs[t - 1] / (fmaxf(nrm[t - 1], 1e-12f) * fmaxf(nrm[t], 1e-12f));
            float act = 1.f / (1.f + expf(-10.f * (0.9f - cosv)));
            float d = prop[t] - prop[t - 1];
            eff = fminf(fmaxf(d * act, 0.f), 1.f);
        }
        local += eff;
        v[i] = local;  // inclusive within thread
    }
    s_sum[tid] = local;
    atomicAdd(&s_amcnt, amc);
    {   // tm count: 512 ints over 256 threads
        int tmc = tm[tid] + tm[tid + 256];
        atomicAdd(&s_tmcnt, tmc);
    }
    __syncthreads();

    // Hillis-Steele inclusive scan over 256 thread totals
    for (int off = 1; off < 256; off <<= 1) {
        float x = (tid >= off) ? s_sum[tid - off] : 0.f;
        __syncthreads();
        s_sum[tid] += x;
        __syncthreads();
    }
    float excl = s_sum[tid] - local;
#pragma unroll
    for (int i = 0; i < PER; i++) s_raw[base + i] = excl + v[i];
    __syncthreads();

    if (tid == 0) {
        int last = max(s_amcnt - 1, 0);
        float lastval = s_raw[last] * (float)am[last];
        lastval = fmaxf(lastval, 1e-6f);
        float tl = (float)s_tmcnt;
        s_scale = fmaxf(tl - 1.f, 0.f) / lastval;
    }
    __syncthreads();
    float scale = s_scale;

#pragma unroll
    for (int i = 0; i < PER; i++) {
        int t = base + i;
        float iv = s_raw[t] * scale;           // monotone
        g_imv[b * T2 + t] = iv;
        imv_out[b * T2 + t] = iv * (float)am[t];

        // windowed softmax partition: s in [floor(iv)-3, floor(iv)+4] clamped,
        // masked by text_mask. Tail terms underflow float32 -> exact match.
        int fi = (int)floorf(iv);
        int s0 = max(0, fi - 3);
        int s1 = min(T1 - 1, fi + 4);
        float Z = 0.f;
        for (int s = s0; s <= s1; s++) {
            if (tm[s]) {
                float dd = iv - (float)s;
                Z += expf(-10.f * dd * dd);
            }
        }
        g_Z[b * T2 + t] = Z;
    }
}

// ---------------------------------------------------------------------------
// k3: block per (b, s), 128 threads (one per feature).
// Binary search contiguous t-range on monotone imv, accumulate weighted mels.
// ---------------------------------------------------------------------------
__global__ void __launch_bounds__(FF) k3(const float* __restrict__ mels,
                                         const int* __restrict__ mel_mask,
                                         const int* __restrict__ text_mask,
                                         float* __restrict__ aligned,
                                         float* __restrict__ durations) {
    int b = blockIdx.y;
    int s = blockIdx.x;
    int f = threadIdx.x;
    float* outrow = aligned + ((size_t)(b * T1 + s)) * FF;

    if (!text_mask[b * T1 + s]) {          // uniform per block
        outrow[f] = 0.f;
        if (f == 0) durations[b * T1 + s] = 0.f;
        return;
    }

    const float* iv = g_imv + b * T2;
    __shared__ int s_lo, s_hi;
    if (f == 0) {
        float lob = (float)s - 4.5f;
        float hib = (float)s + 4.5f;
        int l = 0, r = T2;
        while (l < r) { int m = (l + r) >> 1; if (iv[m] < lob) l = m + 1; else r = m; }
        int lo = l;
        r = T2;
        while (l < r) { int m = (l + r) >> 1; if (iv[m] <= hib) l = m + 1; else r = m; }
        s_lo = lo; s_hi = l;
    }
    __syncthreads();
    int lo = s_lo, hi = s_hi;

    const float* Z  = g_Z + b * T2;
    const int*   am = mel_mask + b * T2;
    const float* mcol = mels + ((size_t)b * T2) * FF + f;

    float acc = 0.f, dur = 0.f;
    for (int t = lo; t < hi; t++) {
        float v = iv[t];                    // uniform broadcast load
        int fi = (int)floorf(v);
        // membership in the SAME clamped window k2 used for Z
        if (s < fi - 3 || s > fi + 4) continue;
        if (!am[t]) continue;
        float z = Z[t];
        if (z <= 0.f) continue;
        float dd = v - (float)s;
        float w = expf(-10.f * dd * dd) / z;
        dur += w;
        acc += w * mcol[(size_t)t * FF];    // coalesced across f
    }
    outrow[f] = acc / (dur + 1e-8f);
    if (f == 0) durations[b * T1 + s] = dur;
}

// ---------------------------------------------------------------------------
extern "C" void kernel_launch(void* const* d_in, const int* in_sizes, int n_in,
                              void* d_out, int out_size) {
    const float* mels      = (const float*)d_in[0];
    const float* alpha     = (const float*)d_in[1];
    const int*   mel_mask  = (const int*)d_in[2];
    const int*   text_mask = (const int*)d_in[3];

    float* aligned   = (float*)d_out;
    float* durations = aligned + (size_t)BB * T1 * FF;
    float* imv_out   = durations + (size_t)BB * T1;

    // k1: warp per (b,t) row -> 32768 warps, 8 warps/block
    k1<<<NBT / 8, 256>>>(mels, alpha);
    // k2: block per batch
    k2<<<BB, 256>>>(mel_mask, text_mask, imv_out);
    // k3: block per (b, s)
    dim3 g3(T1, BB);
    k3<<<g3, FF>>>(mels, mel_mask, text_mask, aligned, durations);
}

// round 4
// speedup vs baseline: 2.6995x; 2.6995x over previous
#include <cuda_runtime.h>
#include <math.h>

#define BB 16
#define T2 2048
#define T1 512
#define FF 128
#define NBT (BB*T2)
#define TS 4   // phonemes per k3 block

// scratch (allocation-free rule: __device__ globals)
__device__ double g_prop[NBT];
__device__ float  g_nrm[NBT];
__device__ float  g_crs[NBT];
__device__ float  g_imv[NBT];   // monotone (pre-mask) imv
__device__ float  g_Z[NBT];     // windowed softmax partition per frame

__device__ __forceinline__ float warpsumf(float v) {
#pragma unroll
    for (int o = 16; o > 0; o >>= 1) v += __shfl_down_sync(0xffffffffu, v, o);
    return v;
}
__device__ __forceinline__ double warpsumd(double v) {
#pragma unroll
    for (int o = 16; o > 0; o >>= 1) v += __shfl_down_sync(0xffffffffu, v, o);
    return v;
}

// ---------------------------------------------------------------------------
// k1: warp per (b,t) row; block = 8 consecutive rows sharing mels via smem.
//  prop[r] = sum_s alpha[r,s]*s   (64 MB read — dominant; double accumulate)
//  nrm[r]  = ||mels[r,:]||
//  crs[r]  = dot(mels[r,:], mels[r+1,:]) for t < T2-1
// ---------------------------------------------------------------------------
__global__ void __launch_bounds__(256) k1(const float* __restrict__ mels,
                                          const float* __restrict__ alpha) {
    int w    = threadIdx.x >> 5;
    int lane = threadIdx.x & 31;
    int row  = blockIdx.x * 8 + w;          // NBT divisible by 8; T2 % 8 == 0
    int t    = row % T2;

    __shared__ float4 s_mel[8 * 32];

    // alpha * index, accumulated in double (group of 4 in fp32, add in fp64)
    const float4* A = reinterpret_cast<const float4*>(alpha + (size_t)row * T1);
    double ps = 0.0;
#pragma unroll
    for (int j = 0; j < 4; j++) {
        int i4 = j * 32 + lane;
        float4 a = A[i4];
        float base = (float)(i4 * 4);
        float s4 = a.x * base + a.y * (base + 1.f) + a.z * (base + 2.f) + a.w * (base + 3.f);
        ps += (double)s4;
    }

    const float4* M = reinterpret_cast<const float4*>(mels + (size_t)row * FF);
    float4 m = M[lane];
    s_mel[w * 32 + lane] = m;
    float ns = m.x * m.x + m.y * m.y + m.z * m.z + m.w * m.w;

    ps = warpsumd(ps);
    ns = warpsumf(ns);
    __syncthreads();

    float cs = 0.f;
    bool has_next = (t < T2 - 1);
    if (has_next) {
        float4 m2 = (w < 7) ? s_mel[(w + 1) * 32 + lane] : M[32 + lane];
        cs = m.x * m2.x + m.y * m2.y + m.z * m2.z + m.w * m2.w;
    }
    cs = warpsumf(cs);

    if (lane == 0) {
        g_prop[row] = ps;
        g_nrm[row]  = sqrtf(ns);
        if (has_next) g_crs[row] = cs;
    }
}

// ---------------------------------------------------------------------------
// k2: one block per batch. activity -> eff_delta -> double block scan ->
// rescale -> imv (output + monotone scratch) and windowed partition Z[t].
// ---------------------------------------------------------------------------
__global__ void __launch_bounds__(256) k2(const int* __restrict__ mel_mask,
                                          const int* __restrict__ text_mask,
                                          float* __restrict__ imv_out) {
    const int PER = T2 / 256;  // 8
    int b = blockIdx.x;
    int tid = threadIdx.x;

    __shared__ double s_raw[T2];      // 16 KB
    __shared__ double s_sum[256];
    __shared__ int s_amcnt, s_tmcnt;
    __shared__ double s_scale;
    if (tid == 0) { s_amcnt = 0; s_tmcnt = 0; }
    __syncthreads();

    const double* prop = g_prop + b * T2;
    const float*  nrm  = g_nrm  + b * T2;
    const float*  crs  = g_crs  + b * T2;
    const int* am = mel_mask  + b * T2;
    const int* tm = text_mask + b * T1;

    double v[PER];
    double local = 0.0;
    int amc = 0;
    int base = tid * PER;
#pragma unroll
    for (int i = 0; i < PER; i++) {
        int t = base + i;
        int a = am[t];
        amc += a;
        float eff = 0.f;
        if (t > 0 && a) {
            float cosv = crs[t - 1] / (fmaxf(nrm[t - 1], 1e-12f) * fmaxf(nrm[t], 1e-12f));
            float act = 1.f / (1.f + expf(-10.f * (0.9f - cosv)));
            float d = (float)(prop[t] - prop[t - 1]);
            eff = fminf(fmaxf(d * act, 0.f), 1.f);
        }
        local += (double)eff;
        v[i] = local;  // inclusive within thread
    }
    s_sum[tid] = local;
    atomicAdd(&s_amcnt, amc);
    atomicAdd(&s_tmcnt, tm[tid] + tm[tid + 256]);
    __syncthreads();

    // Hillis-Steele inclusive scan over thread totals (double)
    for (int off = 1; off < 256; off <<= 1) {
        double x = (tid >= off) ? s_sum[tid - off] : 0.0;
        __syncthreads();
        s_sum[tid] += x;
        __syncthreads();
    }
    double excl = s_sum[tid] - local;
#pragma unroll
    for (int i = 0; i < PER; i++) s_raw[base + i] = excl + v[i];
    __syncthreads();

    if (tid == 0) {
        int last = max(s_amcnt - 1, 0);
        double lastval = s_raw[last] * (double)am[last];
        lastval = fmax(lastval, 1e-6);
        double tl = (double)s_tmcnt;
        s_scale = fmax(tl - 1.0, 0.0) / lastval;
    }
    __syncthreads();
    double scale = s_scale;

#pragma unroll
    for (int i = 0; i < PER; i++) {
        int t = base + i;
        float iv = (float)(s_raw[t] * scale);   // monotone
        g_imv[b * T2 + t] = iv;
        imv_out[b * T2 + t] = iv * (float)am[t];

        // windowed softmax partition: s in [floor(iv)-3, floor(iv)+4] clamped;
        // dropped tail terms underflow fp32 -> exact in float.
        int fi = (int)floorf(iv);
        int s0 = max(0, fi - 3);
        int s1 = min(T1 - 1, fi + 4);
        float Z = 0.f;
        for (int s = s0; s <= s1; s++) {
            if (tm[s]) {
                float dd = iv - (float)s;
                Z += expf(-10.f * dd * dd);
            }
        }
        g_Z[b * T2 + t] = Z;
    }
}

// ---------------------------------------------------------------------------
// k3: block per (b, 4-phoneme tile), 128 threads.
// Phase A (thread-per-frame): compute w(t, s) ONCE into shared.
// Phase B (thread-per-feature): accumulate acc[k] += w * mels[t,f].
// ---------------------------------------------------------------------------
__global__ void __launch_bounds__(FF) k3(const float* __restrict__ mels,
                                         const int* __restrict__ mel_mask,
                                         const int* __restrict__ text_mask,
                                         float* __restrict__ aligned,
                                         float* __restrict__ durations) {
    int b  = blockIdx.y;
    int sb = blockIdx.x * TS;
    int f  = threadIdx.x;
    int wid = f >> 5, lane = f & 31;

    const float* iv = g_imv + b * T2;
    __shared__ int s_lo, s_hi;
    __shared__ float s_w[TS * 128];
    __shared__ float s_part[4 * TS];
    __shared__ float s_dur[TS];

    if (f == 0) {
        // union window: iv in [sb-4.5, sb+TS-1+4.5] covers every (t,s) member
        float lob = (float)sb - 4.5f;
        float hib = (float)(sb + TS - 1) + 4.5f;
        int l = 0, r = T2;
        while (l < r) { int mm = (l + r) >> 1; if (iv[mm] < lob) l = mm + 1; else r = mm; }
        int lo = l;
        r = T2;
        while (l < r) { int mm = (l + r) >> 1; if (iv[mm] <= hib) l = mm + 1; else r = mm; }
        s_lo = lo; s_hi = l;
    }
    if (f < TS) s_dur[f] = 0.f;
    __syncthreads();
    int lo = s_lo, hi = s_hi;

    const int*   am = mel_mask + b * T2;
    const int*   tm = text_mask + b * T1;
    const float* Z  = g_Z + b * T2;
    const float* mcol = mels + ((size_t)b * T2) * FF + f;

    float acc[TS] = {0.f, 0.f, 0.f, 0.f};

    for (int c0 = lo; c0 < hi; c0 += 128) {
        int t = c0 + f;
        float w[TS] = {0.f, 0.f, 0.f, 0.f};
        if (t < hi && am[t]) {
            float v = iv[t];
            float z = Z[t];
            if (z > 0.f) {
                int fi = (int)floorf(v);
#pragma unroll
                for (int k = 0; k < TS; k++) {
                    int s = sb + k;
                    if (s >= fi - 3 && s <= fi + 4 && tm[s]) {
                        float dd = v - (float)s;
                        w[k] = expf(-10.f * dd * dd) / z;
                    }
                }
            }
        }
#pragma unroll
        for (int k = 0; k < TS; k++) {
            s_w[k * 128 + f] = w[k];
            float ws = warpsumf(w[k]);
            if (lane == 0) s_part[wid * TS + k] = ws;
        }
        __syncthreads();
        if (f < TS)
            s_dur[f] += s_part[0 * TS + f] + s_part[1 * TS + f]
                      + s_part[2 * TS + f] + s_part[3 * TS + f];

        int n = min(hi - c0, 128);
        int nfull = n & ~7;
        for (int tt = 0; tt < nfull; tt += 8) {
            float mv[8];
#pragma unroll
            for (int u = 0; u < 8; u++)
                mv[u] = mcol[(size_t)(c0 + tt + u) * FF];   // batched loads -> MLP
#pragma unroll
            for (int u = 0; u < 8; u++) {
#pragma unroll
                for (int k = 0; k < TS; k++)
                    acc[k] += s_w[k * 128 + tt + u] * mv[u]; // broadcast LDS
            }
        }
        for (int tt = nfull; tt < n; tt++) {
            float mval = mcol[(size_t)(c0 + tt) * FF];
#pragma unroll
            for (int k = 0; k < TS; k++)
                acc[k] += s_w[k * 128 + tt] * mval;
        }
        __syncthreads();
    }

#pragma unroll
    for (int k = 0; k < TS; k++) {
        int s = sb + k;
        float d = s_dur[k];
        aligned[((size_t)(b * T1 + s)) * FF + f] = acc[k] / (d + 1e-8f);
        if (f == k) durations[b * T1 + s] = d;
    }
}

// ---------------------------------------------------------------------------
extern "C" void kernel_launch(void* const* d_in, const int* in_sizes, int n_in,
                              void* d_out, int out_size) {
    const float* mels      = (const float*)d_in[0];
    const float* alpha     = (const float*)d_in[1];
    const int*   mel_mask  = (const int*)d_in[2];
    const int*   text_mask = (const int*)d_in[3];

    float* aligned   = (float*)d_out;
    float* durations = aligned + (size_t)BB * T1 * FF;
    float* imv_out   = durations + (size_t)BB * T1;

    k1<<<NBT / 8, 256>>>(mels, alpha);
    k2<<<BB, 256>>>(mel_mask, text_mask, imv_out);
    dim3 g3(T1 / TS, BB);
    k3<<<g3, FF>>>(mels, mel_mask, text_mask, aligned, durations);
}

// round 9
// speedup vs baseline: 3.9699x; 1.4706x over previous
#include <cuda_runtime.h>
#include <math.h>

#define BB 16
#define T2 2048
#define T1 512
#define FF 128
#define NBT (BB*T2)
#define TS 4   // phonemes per k3 block

// scratch (allocation-free rule: __device__ globals)
__device__ float g_prop[NBT];
__device__ float g_nrm[NBT];
__device__ float g_crs[NBT];
__device__ float g_imv[NBT];   // monotone (pre-mask) imv

__device__ __forceinline__ float warpsumf(float v) {
#pragma unroll
    for (int o = 16; o > 0; o >>= 1) v += __shfl_down_sync(0xffffffffu, v, o);
    return v;
}

// ---------------------------------------------------------------------------
// k1: warp per (b,t) row. Pure fp32, independent warps, no barriers.
//  prop[r] = sum_s alpha[r,s]*s   (64 MB read — dominant; LDG-issue bound)
//  nrm[r]  = ||mels[r,:]||
//  crs[r]  = dot(mels[r,:], mels[r+1,:]) for t < T2-1
// ---------------------------------------------------------------------------
__global__ void __launch_bounds__(256) k1(const float* __restrict__ mels,
                                          const float* __restrict__ alpha) {
    int warp = (blockIdx.x * blockDim.x + threadIdx.x) >> 5;
    int lane = threadIdx.x & 31;
    if (warp >= NBT) return;
    int t = warp % T2;

    const float4* A = reinterpret_cast<const float4*>(alpha + (size_t)warp * T1);
    float ps = 0.f;
#pragma unroll
    for (int j = 0; j < 4; j++) {
        int i4 = j * 32 + lane;
        float4 a = A[i4];
        float base = (float)(i4 * 4);
        ps += a.x * base + a.y * (base + 1.f) + a.z * (base + 2.f) + a.w * (base + 3.f);
    }

    const float4* M = reinterpret_cast<const float4*>(mels + (size_t)warp * FF);
    float4 m = M[lane];
    float ns = m.x * m.x + m.y * m.y + m.z * m.z + m.w * m.w;
    float cs = 0.f;
    bool has_next = (t < T2 - 1);
    if (has_next) {
        float4 m2 = M[32 + lane];
        cs = m.x * m2.x + m.y * m2.y + m.z * m2.z + m.w * m2.w;
    }
    ps = warpsumf(ps);
    ns = warpsumf(ns);
    cs = warpsumf(cs);
    if (lane == 0) {
        g_prop[warp] = ps;
        g_nrm[warp]  = sqrtf(ns);
        if (has_next) g_crs[warp] = cs;
    }
}

// ---------------------------------------------------------------------------
// k2: one block per batch. activity -> eff_delta -> double block scan ->
// rescale -> imv (output + monotone scratch). No Z here (moved into k3).
// FP64 count is tiny (16 blocks only), scan precision kept.
// ---------------------------------------------------------------------------
__global__ void __launch_bounds__(256) k2(const int* __restrict__ mel_mask,
                                          const int* __restrict__ text_mask,
                                          float* __restrict__ imv_out) {
    const int PER = T2 / 256;  // 8
    int b = blockIdx.x;
    int tid = threadIdx.x;

    __shared__ double s_sum[256];
    __shared__ int s_amcnt, s_tmcnt;
    __shared__ double s_scale;
    __shared__ double s_last;
    if (tid == 0) { s_amcnt = 0; s_tmcnt = 0; }
    __syncthreads();

    const float* prop = g_prop + b * T2;
    const float* nrm  = g_nrm  + b * T2;
    const float* crs  = g_crs  + b * T2;
    const int* am = mel_mask  + b * T2;
    const int* tm = text_mask + b * T1;

    double v[PER];
    double local = 0.0;
    int amc = 0;
    int base = tid * PER;
#pragma unroll
    for (int i = 0; i < PER; i++) {
        int t = base + i;
        int a = am[t];
        amc += a;
        float eff = 0.f;
        if (t > 0 && a) {
            float cosv = crs[t - 1] / (fmaxf(nrm[t - 1], 1e-12f) * fmaxf(nrm[t], 1e-12f));
            float act = 1.f / (1.f + expf(-10.f * (0.9f - cosv)));
            float d = prop[t] - prop[t - 1];
            eff = fminf(fmaxf(d * act, 0.f), 1.f);
        }
        local += (double)eff;
        v[i] = local;  // inclusive within thread
    }
    s_sum[tid] = local;
    atomicAdd(&s_amcnt, amc);
    atomicAdd(&s_tmcnt, tm[tid] + tm[tid + 256]);
    __syncthreads();

    // Hillis-Steele inclusive scan over thread totals (double)
    for (int off = 1; off < 256; off <<= 1) {
        double x = (tid >= off) ? s_sum[tid - off] : 0.0;
        __syncthreads();
        s_sum[tid] += x;
        __syncthreads();
    }
    double excl = s_sum[tid] - local;

    // raw value at last valid index (owned by exactly one thread)
    {
        int last = max(s_amcnt - 1, 0);
        if (last >= base && last < base + PER)
            s_last = (excl + v[last - base]) * (double)am[last];
    }
    __syncthreads();
    if (tid == 0) {
        double lastval = fmax(s_last, 1e-6);
        s_scale = fmax((double)s_tmcnt - 1.0, 0.0) / lastval;
    }
    __syncthreads();
    double scale = s_scale;

#pragma unroll
    for (int i = 0; i < PER; i++) {
        int t = base + i;
        float iv = (float)((excl + v[i]) * scale);   // monotone
        g_imv[b * T2 + t] = iv;
        imv_out[b * T2 + t] = iv * (float)am[t];
    }
}

// ---------------------------------------------------------------------------
// k3: block per (b, 4-phoneme tile), 128 threads.
// Phase A (thread-per-frame): compute Z and w(t, s) ONCE into shared.
// Phase B (thread-per-feature): accumulate acc[k] += w * mels[t,f].
// ---------------------------------------------------------------------------
__global__ void __launch_bounds__(FF) k3(const float* __restrict__ mels,
                                         const int* __restrict__ mel_mask,
                                         const int* __restrict__ text_mask,
                                         float* __restrict__ aligned,
                                         float* __restrict__ durations) {
    int b  = blockIdx.y;
    int sb = blockIdx.x * TS;
    int f  = threadIdx.x;
    int wid = f >> 5, lane = f & 31;

    const float* iv = g_imv + b * T2;
    __shared__ int s_lo, s_hi;
    __shared__ float s_w[TS * 128];
    __shared__ float s_part[4 * TS];
    __shared__ float s_dur[TS];

    if (f == 0) {
        // union window: iv in [sb-4.5, sb+TS-1+4.5] covers every (t,s) member
        float lob = (float)sb - 4.5f;
        float hib = (float)(sb + TS - 1) + 4.5f;
        int l = 0, r = T2;
        while (l < r) { int mm = (l + r) >> 1; if (iv[mm] < lob) l = mm + 1; else r = mm; }
        int lo = l;
        r = T2;
        while (l < r) { int mm = (l + r) >> 1; if (iv[mm] <= hib) l = mm + 1; else r = mm; }
        s_lo = lo; s_hi = l;
    }
    if (f < TS) s_dur[f] = 0.f;
    __syncthreads();
    int lo = s_lo, hi = s_hi;

    const int*   am = mel_mask + b * T2;
    const int*   tm = text_mask + b * T1;
    const float* mcol = mels + ((size_t)b * T2) * FF + f;

    float acc[TS] = {0.f, 0.f, 0.f, 0.f};

    for (int c0 = lo; c0 < hi; c0 += 128) {
        int t = c0 + f;
        float w[TS] = {0.f, 0.f, 0.f, 0.f};
        if (t < hi && am[t]) {
            float v = iv[t];
            int fi = (int)floorf(v);
            // windowed softmax partition; dropped tail terms underflow fp32
            int s0 = max(0, fi - 3);
            int s1 = min(T1 - 1, fi + 4);
            float Z = 0.f;
            for (int s = s0; s <= s1; s++) {
                if (tm[s]) {
                    float dd = v - (float)s;
                    Z += expf(-10.f * dd * dd);
                }
            }
            if (Z > 0.f) {
#pragma unroll
                for (int k = 0; k < TS; k++) {
                    int s = sb + k;
                    if (s >= fi - 3 && s <= fi + 4 && tm[s]) {
                        float dd = v - (float)s;
                        w[k] = expf(-10.f * dd * dd) / Z;
                    }
                }
            }
        }
#pragma unroll
        for (int k = 0; k < TS; k++) {
            s_w[k * 128 + f] = w[k];
            float ws = warpsumf(w[k]);
            if (lane == 0) s_part[wid * TS + k] = ws;
        }
        __syncthreads();
        if (f < TS)
            s_dur[f] += s_part[0 * TS + f] + s_part[1 * TS + f]
                      + s_part[2 * TS + f] + s_part[3 * TS + f];

        int n = min(hi - c0, 128);
        int nfull = n & ~7;
        for (int tt = 0; tt < nfull; tt += 8) {
            float mv[8];
#pragma unroll
            for (int u = 0; u < 8; u++)
                mv[u] = mcol[(size_t)(c0 + tt + u) * FF];   // batched loads -> MLP
#pragma unroll
            for (int u = 0; u < 8; u++) {
#pragma unroll
                for (int k = 0; k < TS; k++)
                    acc[k] += s_w[k * 128 + tt + u] * mv[u]; // broadcast LDS
            }
        }
        for (int tt = nfull; tt < n; tt++) {
            float mval = mcol[(size_t)(c0 + tt) * FF];
#pragma unroll
            for (int k = 0; k < TS; k++)
                acc[k] += s_w[k * 128 + tt] * mval;
        }
        __syncthreads();
    }

#pragma unroll
    for (int k = 0; k < TS; k++) {
        int s = sb + k;
        float d = s_dur[k];
        aligned[((size_t)(b * T1 + s)) * FF + f] = acc[k] / (d + 1e-8f);
        if (f == k) durations[b * T1 + s] = d;
    }
}

// ---------------------------------------------------------------------------
extern "C" void kernel_launch(void* const* d_in, const int* in_sizes, int n_in,
                              void* d_out, int out_size) {
    const float* mels      = (const float*)d_in[0];
    const float* alpha     = (const float*)d_in[1];
    const int*   mel_mask  = (const int*)d_in[2];
    const int*   text_mask = (const int*)d_in[3];

    float* aligned   = (float*)d_out;
    float* durations = aligned + (size_t)BB * T1 * FF;
    float* imv_out   = durations + (size_t)BB * T1;

    k1<<<NBT / 8, 256>>>(mels, alpha);
    k2<<<BB, 256>>>(mel_mask, text_mask, imv_out);
    dim3 g3(T1 / TS, BB);
    k3<<<g3, FF>>>(mels, mel_mask, text_mask, aligned, durations);
}

// round 10
// speedup vs baseline: 4.6745x; 1.1775x over previous
#include <cuda_runtime.h>
#include <math.h>

#define BB 16
#define T2 2048
#define T1 512
#define FF 128
#define NBT (BB*T2)
#define TS 8   // phonemes per k3 block

// scratch (allocation-free rule: __device__ globals)
__device__ float g_prop[NBT];
__device__ float g_nrm[NBT];
__device__ float g_crs[NBT];
__device__ float g_imv[NBT];   // monotone (pre-mask) imv

__device__ __forceinline__ float warpsumf(float v) {
#pragma unroll
    for (int o = 16; o > 0; o >>= 1) v += __shfl_down_sync(0xffffffffu, v, o);
    return v;
}

// ---------------------------------------------------------------------------
// k1: warp per (b,t) row. Pure fp32, independent warps, no barriers.
//  prop[r] = sum_s alpha[r,s]*s   (64 MB streaming read — dominant)
//  nrm[r]  = ||mels[r,:]||
//  crs[r]  = dot(mels[r,:], mels[r+1,:]) for t < T2-1
// alpha loaded with __ldcs (evict-first) so mels stays L2-resident for k3.
// ---------------------------------------------------------------------------
__global__ void __launch_bounds__(256) k1(const float* __restrict__ mels,
                                          const float* __restrict__ alpha) {
    int warp = (blockIdx.x * blockDim.x + threadIdx.x) >> 5;
    int lane = threadIdx.x & 31;
    if (warp >= NBT) return;
    int t = warp % T2;

    const float4* A = reinterpret_cast<const float4*>(alpha + (size_t)warp * T1);
    float ps = 0.f;
#pragma unroll
    for (int j = 0; j < 4; j++) {
        int i4 = j * 32 + lane;
        float4 a = __ldcs(&A[i4]);
        float base = (float)(i4 * 4);
        ps += a.x * base + a.y * (base + 1.f) + a.z * (base + 2.f) + a.w * (base + 3.f);
    }

    const float4* M = reinterpret_cast<const float4*>(mels + (size_t)warp * FF);
    float4 m = M[lane];
    float ns = m.x * m.x + m.y * m.y + m.z * m.z + m.w * m.w;
    float cs = 0.f;
    bool has_next = (t < T2 - 1);
    if (has_next) {
        float4 m2 = M[32 + lane];
        cs = m.x * m2.x + m.y * m2.y + m.z * m2.z + m.w * m2.w;
    }
    ps = warpsumf(ps);
    ns = warpsumf(ns);
    cs = warpsumf(cs);
    if (lane == 0) {
        g_prop[warp] = ps;
        g_nrm[warp]  = sqrtf(ns);
        if (has_next) g_crs[warp] = cs;
    }
}

// ---------------------------------------------------------------------------
// k2: one block per batch. activity -> eff_delta -> double block scan ->
// rescale -> imv (output + monotone scratch).
// ---------------------------------------------------------------------------
__global__ void __launch_bounds__(256) k2(const int* __restrict__ mel_mask,
                                          const int* __restrict__ text_mask,
                                          float* __restrict__ imv_out) {
    const int PER = T2 / 256;  // 8
    int b = blockIdx.x;
    int tid = threadIdx.x;

    __shared__ double s_sum[256];
    __shared__ int s_amcnt, s_tmcnt;
    __shared__ double s_scale;
    __shared__ double s_last;
    if (tid == 0) { s_amcnt = 0; s_tmcnt = 0; }
    __syncthreads();

    const float* prop = g_prop + b * T2;
    const float* nrm  = g_nrm  + b * T2;
    const float* crs  = g_crs  + b * T2;
    const int* am = mel_mask  + b * T2;
    const int* tm = text_mask + b * T1;

    double v[PER];
    double local = 0.0;
    int amc = 0;
    int base = tid * PER;
#pragma unroll
    for (int i = 0; i < PER; i++) {
        int t = base + i;
        int a = am[t];
        amc += a;
        float eff = 0.f;
        if (t > 0 && a) {
            float cosv = crs[t - 1] / (fmaxf(nrm[t - 1], 1e-12f) * fmaxf(nrm[t], 1e-12f));
            float act = 1.f / (1.f + __expf(-10.f * (0.9f - cosv)));
            float d = prop[t] - prop[t - 1];
            eff = fminf(fmaxf(d * act, 0.f), 1.f);
        }
        local += (double)eff;
        v[i] = local;  // inclusive within thread
    }
    s_sum[tid] = local;
    atomicAdd(&s_amcnt, amc);
    atomicAdd(&s_tmcnt, tm[tid] + tm[tid + 256]);
    __syncthreads();

    // Hillis-Steele inclusive scan over thread totals (double)
    for (int off = 1; off < 256; off <<= 1) {
        double x = (tid >= off) ? s_sum[tid - off] : 0.0;
        __syncthreads();
        s_sum[tid] += x;
        __syncthreads();
    }
    double excl = s_sum[tid] - local;

    // raw value at last valid index (owned by exactly one thread)
    {
        int last = max(s_amcnt - 1, 0);
        if (last >= base && last < base + PER)
            s_last = (excl + v[last - base]) * (double)am[last];
    }
    __syncthreads();
    if (tid == 0) {
        double lastval = fmax(s_last, 1e-6);
        s_scale = fmax((double)s_tmcnt - 1.0, 0.0) / lastval;
    }
    __syncthreads();
    double scale = s_scale;

#pragma unroll
    for (int i = 0; i < PER; i++) {
        int t = base + i;
        float iv = (float)((excl + v[i]) * scale);   // monotone
        g_imv[b * T2 + t] = iv;
        imv_out[b * T2 + t] = iv * (float)am[t];
    }
}

// ---------------------------------------------------------------------------
// k3: block per (b, 8-phoneme tile), 128 threads.
// Phase A (thread-per-frame): compute Z and w(t, s) ONCE into shared.
// Phase B (thread-per-feature): accumulate acc[k] += w * mels[t,f].
// ---------------------------------------------------------------------------
__global__ void __launch_bounds__(FF) k3(const float* __restrict__ mels,
                                         const int* __restrict__ mel_mask,
                                         const int* __restrict__ text_mask,
                                         float* __restrict__ aligned,
                                         float* __restrict__ durations) {
    int b  = blockIdx.y;
    int sb = blockIdx.x * TS;
    int f  = threadIdx.x;
    int wid = f >> 5, lane = f & 31;

    const float* iv = g_imv + b * T2;
    __shared__ int s_lo, s_hi;
    __shared__ float s_w[TS * 128];
    __shared__ float s_part[4 * TS];
    __shared__ float s_dur[TS];

    if (f == 0) {
        // union window: iv in [sb-4.5, sb+TS-1+4.5] covers every (t,s) member
        float lob = (float)sb - 4.5f;
        float hib = (float)(sb + TS - 1) + 4.5f;
        int l = 0, r = T2;
        while (l < r) { int mm = (l + r) >> 1; if (iv[mm] < lob) l = mm + 1; else r = mm; }
        int lo = l;
        r = T2;
        while (l < r) { int mm = (l + r) >> 1; if (iv[mm] <= hib) l = mm + 1; else r = mm; }
        s_lo = lo; s_hi = l;
    }
    if (f < TS) s_dur[f] = 0.f;
    __syncthreads();
    int lo = s_lo, hi = s_hi;

    const int*   am = mel_mask + b * T2;
    const int*   tm = text_mask + b * T1;
    const float* mcol = mels + ((size_t)b * T2) * FF + f;

    float acc[TS];
#pragma unroll
    for (int k = 0; k < TS; k++) acc[k] = 0.f;

    for (int c0 = lo; c0 < hi; c0 += 128) {
        int t = c0 + f;
        float w[TS];
#pragma unroll
        for (int k = 0; k < TS; k++) w[k] = 0.f;
        if (t < hi && am[t]) {
            float v = iv[t];
            int fi = (int)floorf(v);
            // windowed softmax partition; dropped tail terms underflow fp32
            int s0 = max(0, fi - 3);
            int s1 = min(T1 - 1, fi + 4);
            float Z = 0.f;
            for (int s = s0; s <= s1; s++) {
                if (tm[s]) {
                    float dd = v - (float)s;
                    Z += __expf(-10.f * dd * dd);
                }
            }
            if (Z > 0.f) {
                float rz = 1.f / Z;
#pragma unroll
                for (int k = 0; k < TS; k++) {
                    int s = sb + k;
                    if (s >= fi - 3 && s <= fi + 4 && tm[s]) {
                        float dd = v - (float)s;
                        w[k] = __expf(-10.f * dd * dd) * rz;
                    }
                }
            }
        }
#pragma unroll
        for (int k = 0; k < TS; k++) {
            s_w[k * 128 + f] = w[k];
            float ws = warpsumf(w[k]);
            if (lane == 0) s_part[wid * TS + k] = ws;
        }
        __syncthreads();
        if (f < TS)
            s_dur[f] += s_part[0 * TS + f] + s_part[1 * TS + f]
                      + s_part[2 * TS + f] + s_part[3 * TS + f];

        int n = min(hi - c0, 128);
        int nfull = n & ~7;
        for (int tt = 0; tt < nfull; tt += 8) {
            float mv[8];
#pragma unroll
            for (int u = 0; u < 8; u++)
                mv[u] = mcol[(size_t)(c0 + tt + u) * FF];   // batched loads -> MLP
#pragma unroll
            for (int u = 0; u < 8; u++) {
#pragma unroll
                for (int k = 0; k < TS; k++)
                    acc[k] += s_w[k * 128 + tt + u] * mv[u]; // broadcast LDS
            }
        }
        for (int tt = nfull; tt < n; tt++) {
            float mval = mcol[(size_t)(c0 + tt) * FF];
#pragma unroll
            for (int k = 0; k < TS; k++)
                acc[k] += s_w[k * 128 + tt] * mval;
        }
        __syncthreads();
    }

#pragma unroll
    for (int k = 0; k < TS; k++) {
        int s = sb + k;
        float d = s_dur[k];
        aligned[((size_t)(b * T1 + s)) * FF + f] = acc[k] / (d + 1e-8f);
        if (f == k) durations[b * T1 + s] = d;
    }
}

// ---------------------------------------------------------------------------
extern "C" void kernel_launch(void* const* d_in, const int* in_sizes, int n_in,
                              void* d_out, int out_size) {
    const float* mels      = (const float*)d_in[0];
    const float* alpha     = (const float*)d_in[1];
    const int*   mel_mask  = (const int*)d_in[2];
    const int*   text_mask = (const int*)d_in[3];

    float* aligned   = (float*)d_out;
    float* durations = aligned + (size_t)BB * T1 * FF;
    float* imv_out   = durations + (size_t)BB * T1;

    k1<<<NBT / 8, 256>>>(mels, alpha);
    k2<<<BB, 256>>>(mel_mask, text_mask, imv_out);
    dim3 g3(T1 / TS, BB);
    k3<<<g3, FF>>>(mels, mel_mask, text_mask, aligned, durations);
}